// round 16
// baseline (speedup 1.0000x reference)
#include <cuda_runtime.h>
#include <cstdint>

#define NS 512          // number of sites
#define CHUNK 8         // sites per lane (2 warps x 32 lanes x 8 = 512)
#define THREADS 64      // 2 warps = 1 batch per block
#define GRID_BLOCKS 1184 // 148 SMs x 8 blocks

// A coefficients, plane-major: g_Ap[j][idx]. For pair P (0->(0,0), 1->(0,1),
// 2->(1,1)): plane 3P+0 = A_xx, 3P+1 = A_xy+A_yx, 3P+2 = A_yy - A_xx.
// With s2 = x0^2+x1^2, q = x0*x1, r = x1^2:
//   m_P = A_xx + (q*(A_xy+A_yx) + r*(A_yy - A_xx)) / s2    (== Xn.A.Xn)
// Site n = h*256 + l*8 + k lives at idx = h*256 + k*32 + l.
__device__ float g_Ap[9][NS];

__global__ void prep_A_kernel(const float* __restrict__ mpo) {
    int t = blockIdx.x * blockDim.x + threadIdx.x;
    if (t >= NS * 3) return;
    int p = t >> 9, n = t & (NS - 1);
    const float inv = 1.0f / (1.5707963267948966f + 1e-5f); // 1/PI_HALF
    int li = (p == 2) ? 1 : 0;
    int ri = (p == 0) ? 0 : 1;
    const float* m = mpo + n * 16 + li * 8 + ri * 4;        // mpo[n,li,ri,:,:]
    float c0 = atanf(m[0]) * inv;
    float c1 = (atanf(m[1]) + atanf(m[2])) * inv;
    float c2 = atanf(m[3]) * inv;
    int h = n >> 8, l = (n >> 3) & 31, k = n & 7;
    int idx = h * 256 + k * 32 + l;
    g_Ap[3 * p + 0][idx] = c0;
    g_Ap[3 * p + 1][idx] = c1;
    g_Ap[3 * p + 2][idx] = c2 - c0;
}

// MUFU-based sqrt: sqrt.approx(0) = 0, subnormals flush -> no guard needed.
__device__ __forceinline__ float sqrt_approx(float r2) {
    float r; asm("sqrt.approx.f32 %0, %1;" : "=f"(r) : "f"(r2)); return r;
}
__device__ __forceinline__ float rcp_approx(float a) {
    float r; asm("rcp.approx.f32 %0, %1;" : "=f"(r) : "f"(a)); return r;
}

__global__ void __launch_bounds__(THREADS, 8)
tdvp_kernel(const float* __restrict__ x,
            const float* __restrict__ scale_p,
            float* __restrict__ out,
            int B)
{
    // Double-buffered x staging: 16B slots, pair-major swizzled.
    // Pair (l, j) (sites l*8+2j, l*8+2j+1) at slot j*32 + (l ^ (8j)).
    __shared__ float4 sXB[2][2][128];     // 8192 B
    __shared__ float  sT[2][3];           // warp totals (a,b,d)
    __shared__ float  sWp[2];             // per-warp partial sums

    const int tid  = threadIdx.x;
    const int lane = tid & 31;
    const int warp = tid >> 5;            // 0/1 = which 256-site half

    const float scale = __ldg(scale_p);

    // ---- Load this lane's A coefficients ONCE (72 registers), coalesced.
    float Ar[CHUNK][9];
    #pragma unroll
    for (int k = 0; k < CHUNK; k++) {
        const int idx = warp * 256 + k * 32 + lane;
        #pragma unroll
        for (int j = 0; j < 9; j++) Ar[k][j] = g_Ap[j][idx];
    }

    const int stride = gridDim.x;
    int b = blockIdx.x;
    const int niter = (B - 1 - blockIdx.x) / stride + 1;   // >= 1, uniform in block

    const int j_st = lane & 3;            // staging: this lane's slot column j
    const int l0_b = lane >> 2;

    // ---- Async-copy one batch's 2KB (this warp's half) into buffer `buf`.
    auto issue_copy = [&](int buf, int bb) {
        const char* src = (const char*)x + (size_t)bb * 4096 + warp * 2048;
        #pragma unroll
        for (int t4 = 0; t4 < 4; t4++) {
            int fl = t4 * 32 + lane;                  // chunk index within half
            int l0 = t4 * 8 + l0_b;                   // owner lane of this chunk
            int slot = j_st * 32 + (l0 ^ (j_st << 3));
            uint32_t saddr = (uint32_t)__cvta_generic_to_shared(&sXB[buf][warp][slot]);
            asm volatile("cp.async.ca.shared.global [%0], [%1], 16;"
                         :: "r"(saddr), "l"(src + fl * 16) : "memory");
        }
        asm volatile("cp.async.commit_group;" ::: "memory");
    };

    issue_copy(0, b);   // prologue

    for (int it = 0; it < niter; it++, b += stride) {
        // ---- Overlap: issue next batch's copy, then wait for current.
        if (it + 1 < niter) {
            issue_copy((it + 1) & 1, b + stride);
            asm volatile("cp.async.wait_group 1;" ::: "memory");
        } else {
            asm volatile("cp.async.wait_group 0;" ::: "memory");
        }
        __syncwarp();

        const float4* sx4 = sXB[it & 1][warp];

        // ---- Pass A: unnormalized quadratic form; TWO independent
        //      half-aggregates (lo k=0..3, hi k=4..7) for ILP-2 walks.
        float M00[CHUNK], M01[CHUNK], M11[CHUNK];
        float la = 1.f, lb = 0.f, lD = 1.f;   // lo aggregate
        float ha = 1.f, hb = 0.f, hD = 1.f;   // hi aggregate
        #pragma unroll
        for (int j = 0; j < 4; j++) {
            float4 xv = sx4[j * 32 + (lane ^ (j << 3))];
            #pragma unroll
            for (int c = 0; c < 2; c++) {
                const int k = 2 * j + c;
                float x0 = c ? xv.z : xv.x;
                float x1 = c ? xv.w : xv.y;
                float r  = x1 * x1;
                float s2 = fmaf(x0, x0, r);
                float q  = x0 * x1;
                float inv = rcp_approx(s2);
                float m00 = fmaf(fmaf(q, Ar[k][1], r * Ar[k][2]), inv, Ar[k][0]);
                float m01 = fmaf(fmaf(q, Ar[k][4], r * Ar[k][5]), inv, Ar[k][3]);
                float m11 = fmaf(fmaf(q, Ar[k][7], r * Ar[k][8]), inv, Ar[k][6]);
                M00[k] = m00; M01[k] = m01; M11[k] = m11;
                if (k < 4) {
                    float na = la * m00;
                    lb = fmaf(la, m01, lb * m11);
                    lD = lD * m11;
                    la = na;
                } else {
                    float na = ha * m00;
                    hb = fmaf(ha, m01, hb * m11);
                    hD = hD * m11;
                    ha = na;
                }
            }
        }
        // Full chunk aggregate C = L ∘ H.
        float ca = la * ha;
        float cb = fmaf(la, hb, lb * hD);
        float cd = lD * hD;

        // ---- XOR-butterfly bidirectional scan: block aggregate B plus
        //      exclusive prefix P and exclusive suffix S (both start at I).
        float Ba = ca, Bb = cb, Bd = cd;
        float Pa = 1.f, Pb = 0.f, Pd = 1.f;
        float Sa = 1.f, Sb_ = 0.f, Sd_ = 1.f;
        #pragma unroll
        for (int off = 1; off < 32; off <<= 1) {
            float qa = __shfl_xor_sync(0xffffffffu, Ba, off);
            float qb = __shfl_xor_sync(0xffffffffu, Bb, off);
            float qd = __shfl_xor_sync(0xffffffffu, Bd, off);
            if (lane & off) {
                // partner block precedes: P = Q∘P, B = Q∘B
                Pb = fmaf(qa, Pb, qb * Pd);
                Pa = qa * Pa;
                Pd = qd * Pd;
                Bb = fmaf(qa, Bb, qb * Bd);
                Ba = qa * Ba;
                Bd = qd * Bd;
            } else {
                // partner block follows: S = S∘Q, B = B∘Q
                Sb_ = fmaf(Sa, qb, Sb_ * qd);
                Sa  = Sa * qa;
                Sd_ = Sd_ * qd;
                Bb = fmaf(Ba, qb, Bb * qd);
                Ba = Ba * qa;
                Bd = Bd * qd;
            }
        }
        // B now = this warp's 256-site total (same in all lanes).

        // ---- Publish warp totals; cross-warp combine.
        if (lane == 0) { sT[warp][0] = Ba; sT[warp][1] = Bb; sT[warp][2] = Bd; }
        __syncthreads();
        float C0a = sT[0][0], C0b = sT[0][1];
        float C1b = sT[1][1], C1d = sT[1][2];
        float T01 = fmaf(C0a, C1b, C0b * C1d);   // full-chain (0,1) entry

        // ---- Global seeds from exclusive scans.
        float La, Lb, Sb, Sd;
        if (warp == 0) {
            La = Pa; Lb = Pb;
            Sb = fmaf(Sa, C1b, Sb_ * C1d);
            Sd = Sd_ * C1d;
        } else {
            La = C0a * Pa;
            Lb = fmaf(C0a, Pb, C0b * Pd);
            Sb = Sb_; Sd = Sd_;
        }
        // Half-chain seeds (computed up front so half-aggregates die early).
        float SbL = fmaf(ha, Sb, hb * Sd);   // backward lo seed = H ∘ S_exc col1
        float SdL = hD * Sd;
        float raH = La * la;                 // forward hi seed = (La,Lb) ∘ L row0
        float rbH = fmaf(La, lb, Lb * lD);

        // ---- Backward walks (ILP 2): rn = ||S[n+1] col1|| + eps
        //      (exact 1 at n = NS-1).
        float rn[CHUNK];
        {
            float SbH = Sb, SdH = Sd;
            #pragma unroll
            for (int s = 0; s < 4; s++) {
                const int kh = 7 - s;
                bool lastS = (warp == 1) && (lane == 31) && (kh == 7);
                rn[kh] = lastS ? 1.0f : (sqrt_approx(fmaf(SbH, SbH, SdH * SdH)) + 1e-6f);
                float nb = fmaf(M00[kh], SbH, M01[kh] * SdH);
                SdH = M11[kh] * SdH;
                SbH = nb;

                const int kl = 3 - s;       // never site NS-1
                rn[kl] = sqrt_approx(fmaf(SbL, SbL, SdL * SdL)) + 1e-6f;
                float nb2 = fmaf(M00[kl], SbL, M01[kl] * SdL);
                SdL = M11[kl] * SdL;
                SbL = nb2;
            }
        }

        // ---- Forward walks (ILP 2): pn = ||P[n-1] row0|| + eps (exact 1 at
        //      n = 0); w = 1/(pn*rn); y[n] = T01*w.
        float sumw = 0.f;
        {
            float raL = La, rbL = Lb;
            #pragma unroll
            for (int s = 0; s < 4; s++) {
                const int kl = s;
                bool firstS = (warp == 0) && (lane == 0) && (kl == 0);
                float pn = firstS ? 1.0f : (sqrt_approx(fmaf(raL, raL, rbL * rbL)) + 1e-6f);
                float w = rcp_approx(pn * rn[kl]);
                rn[kl] = w;
                sumw += w;
                float na = raL * M00[kl];
                rbL = fmaf(raL, M01[kl], rbL * M11[kl]);
                raL = na;

                const int kh = s + 4;       // never site 0
                float pn2 = sqrt_approx(fmaf(raH, raH, rbH * rbH)) + 1e-6f;
                float w2 = rcp_approx(pn2 * rn[kh]);
                rn[kh] = w2;
                sumw += w2;
                float na2 = raH * M00[kh];
                rbH = fmaf(raH, M01[kh], rbH * M11[kh]);
                raH = na2;
            }
        }

        // ---- Reduce sum(w): warp butterfly, then the 2 warps via smem.
        #pragma unroll
        for (int off = 16; off; off >>= 1)
            sumw += __shfl_xor_sync(0xffffffffu, sumw, off);
        if (lane == 0) sWp[warp] = sumw;
        __syncthreads();
        float sumB = sWp[0] + sWp[1];

        // relu + L1 normalization folded into one factor (w > 0).
        float c = scale * T01;
        float f = (c > 0.f) ? __fdividef(c, fmaf(c, sumB, 1e-6f)) : 0.f;

        // ---- Stores: warp covers a contiguous 1KB span.
        float* ob = out + (size_t)b * NS + warp * 256 + lane * CHUNK;
        #pragma unroll
        for (int k = 0; k < CHUNK; k += 4) {
            float4 v;
            v.x = rn[k + 0] * f;
            v.y = rn[k + 1] * f;
            v.z = rn[k + 2] * f;
            v.w = rn[k + 3] * f;
            *reinterpret_cast<float4*>(ob + k) = v;
        }
    }
}

extern "C" void kernel_launch(void* const* d_in, const int* in_sizes, int n_in,
                              void* d_out, int out_size) {
    const float* x     = (const float*)d_in[0]; // (B, N, 2)
    const float* mpo   = (const float*)d_in[1]; // (N, 2, 2, 2, 2)
    const float* scale = (const float*)d_in[2]; // scalar
    float* out = (float*)d_out;                 // (B, N)

    int B = in_sizes[0] / (NS * 2);

    prep_A_kernel<<<(NS * 3 + 255) / 256, 256>>>(mpo);
    int blocks = GRID_BLOCKS;
    if (blocks > B) blocks = B;
    tdvp_kernel<<<blocks, THREADS>>>(x, scale, out, B);
}

// round 17
// speedup vs baseline: 1.0218x; 1.0218x over previous
#include <cuda_runtime.h>
#include <cstdint>

#define NS 512          // number of sites
#define CHUNK 8         // sites per lane (2 warps x 32 lanes x 8 = 512)
#define THREADS 64      // 2 warps = 1 batch per block
#define GRID_BLOCKS 1184 // 148 SMs x 8 blocks

// A coefficients, plane-major: g_Ap[j][idx]. For pair P (0->(0,0), 1->(0,1),
// 2->(1,1)): plane 3P+0 = A_xx, 3P+1 = A_xy+A_yx, 3P+2 = A_yy - A_xx.
// With s2 = x0^2+x1^2, q = x0*x1, r = x1^2:
//   m_P = A_xx + (q*(A_xy+A_yx) + r*(A_yy - A_xx)) / s2    (== Xn.A.Xn)
// Site n = h*256 + l*8 + k lives at idx = h*256 + k*32 + l.
__device__ float g_Ap[9][NS];

__global__ void prep_A_kernel(const float* __restrict__ mpo) {
    int t = blockIdx.x * blockDim.x + threadIdx.x;
    if (t >= NS * 3) return;
    int p = t >> 9, n = t & (NS - 1);
    const float inv = 1.0f / (1.5707963267948966f + 1e-5f); // 1/PI_HALF
    int li = (p == 2) ? 1 : 0;
    int ri = (p == 0) ? 0 : 1;
    const float* m = mpo + n * 16 + li * 8 + ri * 4;        // mpo[n,li,ri,:,:]
    float c0 = atanf(m[0]) * inv;
    float c1 = (atanf(m[1]) + atanf(m[2])) * inv;
    float c2 = atanf(m[3]) * inv;
    int h = n >> 8, l = (n >> 3) & 31, k = n & 7;
    int idx = h * 256 + k * 32 + l;
    g_Ap[3 * p + 0][idx] = c0;
    g_Ap[3 * p + 1][idx] = c1;
    g_Ap[3 * p + 2][idx] = c2 - c0;
}

// MUFU-based sqrt: sqrt.approx(0) = 0, subnormals flush -> no guard needed.
__device__ __forceinline__ float sqrt_approx(float r2) {
    float r; asm("sqrt.approx.f32 %0, %1;" : "=f"(r) : "f"(r2)); return r;
}
__device__ __forceinline__ float rcp_approx(float a) {
    float r; asm("rcp.approx.f32 %0, %1;" : "=f"(r) : "f"(a)); return r;
}

__global__ void __launch_bounds__(THREADS, 8)
tdvp_kernel(const float* __restrict__ x,
            const float* __restrict__ scale_p,
            float* __restrict__ out,
            int B)
{
    // Double-buffered x staging: 16B slots, pair-major swizzled.
    // Pair (l, j) (sites l*8+2j, l*8+2j+1) at slot j*32 + (l ^ (8j)).
    __shared__ float4 sXB[2][2][128];     // 8192 B
    __shared__ float  sT[2][3];           // warp totals (a,b,d)
    __shared__ float  sWp[2];             // per-warp partial sums

    const int tid  = threadIdx.x;
    const int lane = tid & 31;
    const int warp = tid >> 5;            // 0/1 = which 256-site half

    const float scale = __ldg(scale_p);

    // ---- Load this lane's A coefficients ONCE (72 registers), coalesced.
    float Ar[CHUNK][9];
    #pragma unroll
    for (int k = 0; k < CHUNK; k++) {
        const int idx = warp * 256 + k * 32 + lane;
        #pragma unroll
        for (int j = 0; j < 9; j++) Ar[k][j] = g_Ap[j][idx];
    }

    const int stride = gridDim.x;
    int b = blockIdx.x;
    const int niter = (B - 1 - blockIdx.x) / stride + 1;   // >= 1, uniform in block

    const int j_st = lane & 3;            // staging: this lane's slot column j
    const int l0_b = lane >> 2;

    // ---- Async-copy one batch's 2KB (this warp's half) into buffer `buf`.
    auto issue_copy = [&](int buf, int bb) {
        const char* src = (const char*)x + (size_t)bb * 4096 + warp * 2048;
        #pragma unroll
        for (int t4 = 0; t4 < 4; t4++) {
            int fl = t4 * 32 + lane;                  // chunk index within half
            int l0 = t4 * 8 + l0_b;                   // owner lane of this chunk
            int slot = j_st * 32 + (l0 ^ (j_st << 3));
            uint32_t saddr = (uint32_t)__cvta_generic_to_shared(&sXB[buf][warp][slot]);
            asm volatile("cp.async.ca.shared.global [%0], [%1], 16;"
                         :: "r"(saddr), "l"(src + fl * 16) : "memory");
        }
        asm volatile("cp.async.commit_group;" ::: "memory");
    };

    issue_copy(0, b);   // prologue

    for (int it = 0; it < niter; it++, b += stride) {
        // ---- Overlap: issue next batch's copy, then wait for current.
        if (it + 1 < niter) {
            issue_copy((it + 1) & 1, b + stride);
            asm volatile("cp.async.wait_group 1;" ::: "memory");
        } else {
            asm volatile("cp.async.wait_group 0;" ::: "memory");
        }
        __syncwarp();

        const float4* sx4 = sXB[it & 1][warp];

        // ---- Pass A: unnormalized quadratic form (no rsqrt/normalize);
        //      build M per site + lane chunk aggregate (8-deep).
        float M00[CHUNK], M01[CHUNK], M11[CHUNK];
        float ca = 1.f, cb = 0.f, cd = 1.f;
        #pragma unroll
        for (int j = 0; j < 4; j++) {
            float4 xv = sx4[j * 32 + (lane ^ (j << 3))];
            #pragma unroll
            for (int c = 0; c < 2; c++) {
                const int k = 2 * j + c;
                float x0 = c ? xv.z : xv.x;
                float x1 = c ? xv.w : xv.y;
                float r  = x1 * x1;
                float s2 = fmaf(x0, x0, r);
                float q  = x0 * x1;
                float inv = rcp_approx(s2);
                float m00 = fmaf(fmaf(q, Ar[k][1], r * Ar[k][2]), inv, Ar[k][0]);
                float m01 = fmaf(fmaf(q, Ar[k][4], r * Ar[k][5]), inv, Ar[k][3]);
                float m11 = fmaf(fmaf(q, Ar[k][7], r * Ar[k][8]), inv, Ar[k][6]);
                M00[k] = m00; M01[k] = m01; M11[k] = m11;
                float na = ca * m00;
                float nb = fmaf(ca, m01, cb * m11);
                cd = cd * m11;
                ca = na; cb = nb;
            }
        }

        // ---- XOR-butterfly bidirectional scan: block aggregate B plus
        //      exclusive prefix P and exclusive suffix S (both start at I).
        float Ba = ca, Bb = cb, Bd = cd;
        float Pa = 1.f, Pb = 0.f, Pd = 1.f;
        float Sa = 1.f, Sb_ = 0.f, Sd_ = 1.f;
        #pragma unroll
        for (int off = 1; off < 32; off <<= 1) {
            float qa = __shfl_xor_sync(0xffffffffu, Ba, off);
            float qb = __shfl_xor_sync(0xffffffffu, Bb, off);
            float qd = __shfl_xor_sync(0xffffffffu, Bd, off);
            if (lane & off) {
                // partner block precedes: P = Q∘P, B = Q∘B
                Pb = fmaf(qa, Pb, qb * Pd);
                Pa = qa * Pa;
                Pd = qd * Pd;
                Bb = fmaf(qa, Bb, qb * Bd);
                Ba = qa * Ba;
                Bd = qd * Bd;
            } else {
                // partner block follows: S = S∘Q, B = B∘Q
                Sb_ = fmaf(Sa, qb, Sb_ * qd);
                Sa  = Sa * qa;
                Sd_ = Sd_ * qd;
                Bb = fmaf(Ba, qb, Bb * qd);
                Ba = Ba * qa;
                Bd = Bd * qd;
            }
        }
        // B now = this warp's 256-site total (same in all lanes).

        // ---- Publish warp totals; cross-warp combine.
        if (lane == 0) { sT[warp][0] = Ba; sT[warp][1] = Bb; sT[warp][2] = Bd; }
        __syncthreads();
        float C0a = sT[0][0], C0b = sT[0][1];
        float C1b = sT[1][1], C1d = sT[1][2];
        float T01 = fmaf(C0a, C1b, C0b * C1d);   // full-chain (0,1) entry

        // ---- Global seeds from exclusive scans.
        float La, Lb, Sb, Sd;
        if (warp == 0) {
            La = Pa; Lb = Pb;
            Sb = fmaf(Sa, C1b, Sb_ * C1d);
            Sd = Sd_ * C1d;
        } else {
            La = C0a * Pa;
            Lb = fmaf(C0a, Pb, C0b * Pd);
            Sb = Sb_; Sd = Sd_;
        }

        // ---- Backward walk: rn = ||S[n+1] col1|| + eps (exact 1 at n=NS-1).
        float rn[CHUNK];
        #pragma unroll
        for (int k = CHUNK - 1; k >= 0; k--) {
            bool lastS = (warp == 1) && (lane == 31) && (k == CHUNK - 1);
            rn[k] = lastS ? 1.0f : (sqrt_approx(fmaf(Sb, Sb, Sd * Sd)) + 1e-6f);
            float nb = fmaf(M00[k], Sb, M01[k] * Sd);
            Sd = M11[k] * Sd;
            Sb = nb;
        }

        // ---- Forward walk: pn = ||P[n-1] row0|| + eps (exact 1 at n=0);
        //      w = 1/(pn*rn); y[n] = T01*w.
        float sumw = 0.f;
        {
            float ra = La, rb = Lb;
            #pragma unroll
            for (int k = 0; k < CHUNK; k++) {
                bool firstS = (warp == 0) && (lane == 0) && (k == 0);
                float pn = firstS ? 1.0f : (sqrt_approx(fmaf(ra, ra, rb * rb)) + 1e-6f);
                float w = rcp_approx(pn * rn[k]);
                rn[k] = w;
                sumw += w;
                float na = ra * M00[k];
                rb = fmaf(ra, M01[k], rb * M11[k]);
                ra = na;
            }
        }

        // ---- Reduce sum(w): warp butterfly, then the 2 warps via smem.
        #pragma unroll
        for (int off = 16; off; off >>= 1)
            sumw += __shfl_xor_sync(0xffffffffu, sumw, off);
        if (lane == 0) sWp[warp] = sumw;
        __syncthreads();
        float sumB = sWp[0] + sWp[1];

        // relu + L1 normalization folded into one factor (w > 0).
        float c = scale * T01;
        float f = (c > 0.f) ? __fdividef(c, fmaf(c, sumB, 1e-6f)) : 0.f;

        // ---- Stores: warp covers a contiguous 1KB span.
        float* ob = out + (size_t)b * NS + warp * 256 + lane * CHUNK;
        #pragma unroll
        for (int k = 0; k < CHUNK; k += 4) {
            float4 v;
            v.x = rn[k + 0] * f;
            v.y = rn[k + 1] * f;
            v.z = rn[k + 2] * f;
            v.w = rn[k + 3] * f;
            *reinterpret_cast<float4*>(ob + k) = v;
        }
    }
}

extern "C" void kernel_launch(void* const* d_in, const int* in_sizes, int n_in,
                              void* d_out, int out_size) {
    const float* x     = (const float*)d_in[0]; // (B, N, 2)
    const float* mpo   = (const float*)d_in[1]; // (N, 2, 2, 2, 2)
    const float* scale = (const float*)d_in[2]; // scalar
    float* out = (float*)d_out;                 // (B, N)

    int B = in_sizes[0] / (NS * 2);

    prep_A_kernel<<<(NS * 3 + 255) / 256, 256>>>(mpo);
    int blocks = GRID_BLOCKS;
    if (blocks > B) blocks = B;
    tdvp_kernel<<<blocks, THREADS>>>(x, scale, out, B);
}